// round 8
// baseline (speedup 1.0000x reference)
#include <cuda_runtime.h>
#include <cuda_bf16.h>
#include <cuda_fp16.h>
#include <cstdint>

// ---------------- problem constants ----------------
#define S_LEN   2048
#define DMODEL  1024
#define DPH     64
#define BM      128
#define BN      128
#define NKT     16
#define NTHREADS 256

#define OUT_ELEMS (2048ULL * 2048ULL)            // B*S*D
#define DOT_ELEMS (32ULL * 2048ULL * 2048ULL)    // B*H*S*S

#define P_SCALE 0.00390625f                      // 2^-8: keep exp() inside fp16 range

// ---------------- smem layout (bytes) ----------------
#define STG_OFF 0          // 32768: raw fp32 tile staging (also Q staging)
#define KB_OFF  32768      // 32768: K tile tf32, swizzled
#define VB_OFF  65536      // 16384: V tile fp16, swizzled
#define MW_OFF  81920      // 256  : mask bit-words
#define SMEM_BYTES 82432

// ---------------- helpers ----------------
static __device__ __forceinline__ uint32_t smem_u32(const void* p) {
    uint32_t a;
    asm("{ .reg .u64 t; cvta.to.shared.u64 t, %1; cvt.u32.u64 %0, t; }" : "=r"(a) : "l"(p));
    return a;
}
static __device__ __forceinline__ uint32_t f2tf32(float f) {
    uint32_t r;
    asm("cvt.rna.tf32.f32 %0, %1;" : "=r"(r) : "f"(f));
    return r;
}
static __device__ __forceinline__ uint32_t pack_f16x2(float lo, float hi) {
    __half2 p = __floats2half2_rn(lo, hi);       // .x = lo (low 16 bits)
    return *reinterpret_cast<uint32_t*>(&p);
}
static __device__ __forceinline__ void mma_tf32(float* c, const uint32_t* a,
                                                uint32_t b0, uint32_t b1) {
    asm volatile(
        "mma.sync.aligned.m16n8k8.row.col.f32.tf32.tf32.f32 "
        "{%0,%1,%2,%3}, {%4,%5,%6,%7}, {%8,%9}, {%0,%1,%2,%3};"
        : "+f"(c[0]), "+f"(c[1]), "+f"(c[2]), "+f"(c[3])
        : "r"(a[0]), "r"(a[1]), "r"(a[2]), "r"(a[3]), "r"(b0), "r"(b1));
}
static __device__ __forceinline__ void mma_f16(float* c, uint32_t a0, uint32_t a1,
                                               uint32_t a2, uint32_t a3,
                                               uint32_t b0, uint32_t b1) {
    asm volatile(
        "mma.sync.aligned.m16n8k16.row.col.f32.f16.f16.f32 "
        "{%0,%1,%2,%3}, {%4,%5,%6,%7}, {%8,%9}, {%0,%1,%2,%3};"
        : "+f"(c[0]), "+f"(c[1]), "+f"(c[2]), "+f"(c[3])
        : "r"(a0), "r"(a1), "r"(a2), "r"(a3), "r"(b0), "r"(b1));
}
static __device__ __forceinline__ void ldsm_x4(uint32_t& r0, uint32_t& r1,
                                               uint32_t& r2, uint32_t& r3, uint32_t addr) {
    asm volatile("ldmatrix.sync.aligned.m8n8.x4.shared.b16 {%0,%1,%2,%3}, [%4];"
                 : "=r"(r0), "=r"(r1), "=r"(r2), "=r"(r3) : "r"(addr));
}
static __device__ __forceinline__ void ldsm_x2t(uint32_t& r0, uint32_t& r1, uint32_t addr) {
    asm volatile("ldmatrix.sync.aligned.m8n8.x2.trans.shared.b16 {%0,%1}, [%2];"
                 : "=r"(r0), "=r"(r1) : "r"(addr));
}

// issue 32KB raw fp32 tile load: 128 rows x 64 floats, row stride DMODEL
static __device__ __forceinline__ void tile_load(uint32_t sdst, const float* g, int tid) {
#pragma unroll
    for (int i = 0; i < 8; ++i) {
        int idx = i * NTHREADS + tid;            // 0..2047 float4s
        int key = idx >> 4, c4 = idx & 15;
        uint32_t sa = sdst + (uint32_t)idx * 16;
        const float* ga = g + (size_t)key * DMODEL + c4 * 4;
        asm volatile("cp.async.cg.shared.global [%0], [%1], 16;" :: "r"(sa), "l"(ga));
    }
    asm volatile("cp.async.commit_group;");
}
#define CP_WAIT0() asm volatile("cp.async.wait_group 0;" ::: "memory")

// ---------------- fused MHA kernel (mma.sync path, sm_100-safe) ----------------
__global__ void __launch_bounds__(NTHREADS, 1)
mha_kernel(const float* __restrict__ X, const int* __restrict__ mask,
           float* __restrict__ out, float* __restrict__ dp) {
    extern __shared__ char smem[];
    const uint32_t sbase = smem_u32(smem);
    float* stgf = reinterpret_cast<float*>(smem + STG_OFF);
    uint32_t* mask_words = reinterpret_cast<uint32_t*>(smem + MW_OFF);

    const int tid  = threadIdx.x;
    const int wid  = tid >> 5;
    const int lane = tid & 31;
    const int qq   = lane & 3;          // quad lane
    const int lr   = (wid << 4) + (lane >> 2);   // local row 0..127 (row group base)

    const int qt = blockIdx.x;
    const int bh = blockIdx.y;
    const int b  = bh >> 4;
    const int h  = bh & 15;

    // ldmatrix address precompute (K: x4 non-trans, V: x2 trans)
    const int rowin16 = ((lane >> 4) & 1) * 8 + (lane & 7);
    const int sb16    = (lane >> 3) & 1;
    const uint32_t kxor  = (uint32_t)((lane & 7) << 4);
    const uint32_t kbase = sbase + KB_OFF + (uint32_t)rowin16 * 256;
    const int i2 = lane & 15;
    const uint32_t vxor  = (uint32_t)((i2 & 7) << 4);
    const uint32_t vbase = sbase + VB_OFF + (uint32_t)i2 * 128;

    // mask bitset: 64 words cover 2048 keys
    for (int j = wid; j < S_LEN / 32; j += 8) {
        int m = mask[b * S_LEN + j * 32 + lane];
        unsigned wv = __ballot_sync(0xFFFFFFFFu, m != 0);
        if (lane == 0) mask_words[j] = wv;
    }

    // ---- prologue: stage Q tile, build Q tf32 fragments in registers ----
    const float* Xbh = X + (size_t)b * S_LEN * DMODEL + (size_t)h * DPH;
    tile_load(sbase + STG_OFF, Xbh + (size_t)(qt * BM) * DMODEL, tid);
    CP_WAIT0();
    __syncthreads();

    uint32_t qa[8][4];
#pragma unroll
    for (int ks = 0; ks < 8; ++ks) {
        qa[ks][0] = f2tf32(stgf[lr * 64 + ks * 8 + qq]);
        qa[ks][1] = f2tf32(stgf[(lr + 8) * 64 + ks * 8 + qq]);
        qa[ks][2] = f2tf32(stgf[lr * 64 + ks * 8 + qq + 4]);
        qa[ks][3] = f2tf32(stgf[(lr + 8) * 64 + ks * 8 + qq + 4]);
    }
    __syncthreads();

    // kick K/V tile 0
    tile_load(sbase + STG_OFF, Xbh, tid);

    // output accumulators + row sums
    float oa[8][4];
#pragma unroll
    for (int nb = 0; nb < 8; ++nb)
#pragma unroll
        for (int j = 0; j < 4; ++j) oa[nb][j] = 0.0f;
    float rs0 = 0.0f, rs1 = 0.0f;

    const int qrow0 = qt * BM + lr;
    float* dpr0 = dp ? dp + ((size_t)bh * S_LEN + qrow0) * S_LEN + 2 * qq : (float*)0;
    float* dpr1 = dpr0 ? dpr0 + 8 * (size_t)S_LEN : (float*)0;

#pragma unroll 1
    for (int kt = 0; kt < NKT; ++kt) {
        CP_WAIT0();
        __syncthreads();     // staging ready; prior compute done with KB/VB

        // ---- convert staging -> K tf32 (swizzled) + V fp16 (swizzled) ----
#pragma unroll
        for (int i = 0; i < 8; ++i) {
            int idx = i * NTHREADS + tid;
            int key = idx >> 4, c4 = idx & 15;
            float4 v = *reinterpret_cast<const float4*>(stgf + idx * 4);
            int ks = c4 >> 1, s = c4 & 1;
            uint32_t koff = (uint32_t)KB_OFF + (uint32_t)key * 256 +
                            (((uint32_t)(ks * 32 + s * 16)) ^ ((uint32_t)(key & 7) << 4));
            *reinterpret_cast<uint4*>(smem + koff) =
                make_uint4(f2tf32(v.x), f2tf32(v.y), f2tf32(v.z), f2tf32(v.w));
            uint32_t voff = (uint32_t)VB_OFF + (uint32_t)key * 128 +
                            (((uint32_t)(c4 * 8)) ^ ((uint32_t)(key & 7) << 4));
            *reinterpret_cast<uint2*>(smem + voff) =
                make_uint2(pack_f16x2(v.x, v.y), pack_f16x2(v.z, v.w));
        }
        __syncthreads();

        if (kt + 1 < NKT)
            tile_load(sbase + STG_OFF, Xbh + (size_t)((kt + 1) * BN) * DMODEL, tid);

        // ---- S = Q K^T (tf32, single pass) ----
        float sa[16][4];
#pragma unroll
        for (int nb = 0; nb < 16; ++nb)
#pragma unroll
            for (int j = 0; j < 4; ++j) sa[nb][j] = 0.0f;

#pragma unroll
        for (int ks = 0; ks < 8; ++ks) {
            uint32_t kss = (uint32_t)(ks * 32 + sb16 * 16);
#pragma unroll
            for (int nbp = 0; nbp < 8; ++nbp) {
                uint32_t b0, b1, b2, b3;
                ldsm_x4(b0, b1, b2, b3, kbase + (uint32_t)nbp * 4096 + (kss ^ kxor));
                mma_tf32(sa[2 * nbp],     qa[ks], b0, b1);
                mma_tf32(sa[2 * nbp + 1], qa[ks], b2, b3);
            }
        }

        // ---- scale, mask, write dot_prod, exp, pack P (fp16x2 = PV A-frags) ----
        uint32_t mwt0 = mask_words[kt * 4 + 0], mwt1 = mask_words[kt * 4 + 1];
        uint32_t mwt2 = mask_words[kt * 4 + 2], mwt3 = mask_words[kt * 4 + 3];
        bool tile_all = ((mwt0 & mwt1 & mwt2 & mwt3) == 0xFFFFFFFFu);

        uint32_t ph0[16], ph1[16];
#pragma unroll
        for (int nb = 0; nb < 16; ++nb) {
            float c0 = sa[nb][0] * 0.125f, c1 = sa[nb][1] * 0.125f;
            float c2 = sa[nb][2] * 0.125f, c3 = sa[nb][3] * 0.125f;
            if (!tile_all) {
                int col = nb * 8 + 2 * qq;
                uint32_t w = (nb < 4) ? mwt0 : (nb < 8) ? mwt1 : (nb < 12) ? mwt2 : mwt3;
                if (!((w >> (col & 31)) & 1u)) { c0 = -1e20f; c2 = -1e20f; }
                if (!((w >> ((col + 1) & 31)) & 1u)) { c1 = -1e20f; c3 = -1e20f; }
            }
            if (dpr0) {
                int coff = kt * BN + nb * 8;
                *reinterpret_cast<float2*>(dpr0 + coff) = make_float2(c0, c1);
                *reinterpret_cast<float2*>(dpr1 + coff) = make_float2(c2, c3);
            }
            // scaled p: keeps fp16 in range; scale cancels in O/rowsum ratio
            float p0 = __expf(c0) * P_SCALE, p1 = __expf(c1) * P_SCALE;
            float p2 = __expf(c2) * P_SCALE, p3 = __expf(c3) * P_SCALE;
            rs0 += p0 + p1;
            rs1 += p2 + p3;
            ph0[nb] = pack_f16x2(p0, p1);
            ph1[nb] = pack_f16x2(p2, p3);
        }

        // ---- O += P V (fp16), V from smem via ldmatrix.trans ----
#pragma unroll
        for (int kg = 0; kg < 8; ++kg) {
            uint32_t a0 = ph0[2 * kg], a1 = ph1[2 * kg];
            uint32_t a2 = ph0[2 * kg + 1], a3 = ph1[2 * kg + 1];
#pragma unroll
            for (int nb = 0; nb < 8; ++nb) {
                uint32_t b0, b1;
                ldsm_x2t(b0, b1, vbase + (uint32_t)kg * 2048 + (((uint32_t)(nb * 16)) ^ vxor));
                mma_f16(oa[nb], a0, a1, a2, a3, b0, b1);
            }
        }
    }

    // ---- finalize: row sums (quad reduce), normalize, store out ----
    rs0 += __shfl_xor_sync(0xFFFFFFFFu, rs0, 1);
    rs0 += __shfl_xor_sync(0xFFFFFFFFu, rs0, 2);
    rs1 += __shfl_xor_sync(0xFFFFFFFFu, rs1, 1);
    rs1 += __shfl_xor_sync(0xFFFFFFFFu, rs1, 2);
    float inv0 = 1.0f / rs0, inv1 = 1.0f / rs1;

    if (out) {
        float* or0 = out + ((size_t)(b * S_LEN + qrow0)) * DMODEL + h * DPH + 2 * qq;
        float* or1 = or0 + 8 * (size_t)DMODEL;
#pragma unroll
        for (int nb = 0; nb < 8; ++nb) {
            *reinterpret_cast<float2*>(or0 + nb * 8) =
                make_float2(oa[nb][0] * inv0, oa[nb][1] * inv0);
            *reinterpret_cast<float2*>(or1 + nb * 8) =
                make_float2(oa[nb][2] * inv1, oa[nb][3] * inv1);
        }
    }
}

// ---------------- launch ----------------
extern "C" void kernel_launch(void* const* d_in, const int* in_sizes, int n_in,
                              void* d_out, int out_size) {
    const float* X  = (const float*)d_in[0];
    const int* mask = (const int*)d_in[1];

    float* out = (float*)0;
    float* dp  = (float*)0;
    size_t os = (size_t)out_size;
    if (os >= OUT_ELEMS + DOT_ELEMS) {
        out = (float*)d_out;
        dp  = (float*)d_out + OUT_ELEMS;
    } else if (os == DOT_ELEMS) {
        dp = (float*)d_out;
    } else {
        out = (float*)d_out;
    }

    cudaFuncSetAttribute(mha_kernel, cudaFuncAttributeMaxDynamicSharedMemorySize, SMEM_BYTES);
    dim3 grid(S_LEN / BM, 32);
    mha_kernel<<<grid, NTHREADS, SMEM_BYTES>>>(X, mask, out, dp);
}

// round 10
// speedup vs baseline: 1.2496x; 1.2496x over previous
#include <cuda_runtime.h>
#include <cuda_fp16.h>
#include <cstdint>

// ---------------- problem constants ----------------
#define S_LEN   2048
#define DMODEL  1024
#define DPH     64
#define BM      128
#define BN      128
#define NKT     16
#define NTHREADS 256

#define OUT_ELEMS (2048ULL * 2048ULL)            // B*S*D
#define DOT_ELEMS (32ULL * 2048ULL * 2048ULL)    // B*H*S*S

#define P_SCALE 0.00390625f                      // 2^-8: keep exp() inside fp16 range

// ---------------- smem layout (bytes) ----------------
#define STG_OFF 0          // 32768: raw fp32 tile staging (also Q staging)
#define KV_OFF  32768      // 16384: KV tile fp16 (K for S-GEMM, V for PV), swizzled
#define MW_OFF  49152      // 256  : mask bit-words
#define SMEM_BYTES 49408

// ---------------- helpers ----------------
static __device__ __forceinline__ uint32_t smem_u32(const void* p) {
    uint32_t a;
    asm("{ .reg .u64 t; cvta.to.shared.u64 t, %1; cvt.u32.u64 %0, t; }" : "=r"(a) : "l"(p));
    return a;
}
static __device__ __forceinline__ uint32_t pack_f16x2(float lo, float hi) {
    __half2 p = __floats2half2_rn(lo, hi);       // .x = lo (low 16 bits)
    return *reinterpret_cast<uint32_t*>(&p);
}
static __device__ __forceinline__ void mma_f16(float* c, uint32_t a0, uint32_t a1,
                                               uint32_t a2, uint32_t a3,
                                               uint32_t b0, uint32_t b1) {
    asm volatile(
        "mma.sync.aligned.m16n8k16.row.col.f32.f16.f16.f32 "
        "{%0,%1,%2,%3}, {%4,%5,%6,%7}, {%8,%9}, {%0,%1,%2,%3};"
        : "+f"(c[0]), "+f"(c[1]), "+f"(c[2]), "+f"(c[3])
        : "r"(a0), "r"(a1), "r"(a2), "r"(a3), "r"(b0), "r"(b1));
}
static __device__ __forceinline__ void ldsm_x4(uint32_t& r0, uint32_t& r1,
                                               uint32_t& r2, uint32_t& r3, uint32_t addr) {
    asm volatile("ldmatrix.sync.aligned.m8n8.x4.shared.b16 {%0,%1,%2,%3}, [%4];"
                 : "=r"(r0), "=r"(r1), "=r"(r2), "=r"(r3) : "r"(addr));
}
static __device__ __forceinline__ void ldsm_x2t(uint32_t& r0, uint32_t& r1, uint32_t addr) {
    asm volatile("ldmatrix.sync.aligned.m8n8.x2.trans.shared.b16 {%0,%1}, [%2];"
                 : "=r"(r0), "=r"(r1) : "r"(addr));
}

// issue 32KB raw fp32 tile load: 128 rows x 64 floats, row stride DMODEL
static __device__ __forceinline__ void tile_load(uint32_t sdst, const float* g, int tid) {
#pragma unroll
    for (int i = 0; i < 8; ++i) {
        int idx = i * NTHREADS + tid;            // 0..2047 float4s
        int key = idx >> 4, c4 = idx & 15;
        uint32_t sa = sdst + (uint32_t)idx * 16;
        const float* ga = g + (size_t)key * DMODEL + c4 * 4;
        asm volatile("cp.async.cg.shared.global [%0], [%1], 16;" :: "r"(sa), "l"(ga));
    }
    asm volatile("cp.async.commit_group;");
}
#define CP_WAIT0() asm volatile("cp.async.wait_group 0;" ::: "memory")

// ---------------- fused MHA kernel (fp16 mma.sync everywhere) ----------------
__global__ void __launch_bounds__(NTHREADS, 1)
mha_kernel(const float* __restrict__ X, const int* __restrict__ mask,
           float* __restrict__ out, float* __restrict__ dp) {
    extern __shared__ char smem[];
    const uint32_t sbase = smem_u32(smem);
    float* stgf = reinterpret_cast<float*>(smem + STG_OFF);
    uint32_t* mask_words = reinterpret_cast<uint32_t*>(smem + MW_OFF);

    const int tid  = threadIdx.x;
    const int wid  = tid >> 5;
    const int lane = tid & 31;
    const int qq   = lane & 3;          // quad lane
    const int lr   = (wid << 4) + (lane >> 2);   // local row 0..127 (row group base)

    const int qt = blockIdx.x;
    const int bh = blockIdx.y;
    const int b  = bh >> 4;
    const int h  = bh & 15;

    // ldmatrix addressing for S-GEMM B (K, non-trans, x4):
    //   lanes 0-7:  K[n0+krow]   [k0..k0+7]     -> b0 (n-block n0,   k lo)
    //   lanes 8-15: K[n0+krow]   [k0+8..k0+15]  -> b1 (n-block n0,   k hi)
    //   lanes 16-23:K[n0+8+krow] [k0..k0+7]     -> b2 (n-block n0+8, k lo)
    //   lanes 24-31:K[n0+8+krow] [k0+8..k0+15]  -> b3 (n-block n0+8, k hi)
    const int krow = lane & 7;
    const int kg1  = (lane >> 3) & 1;    // +8 in k
    const int kg2  = (lane >> 4) & 1;    // +8 in n
    const uint32_t kxor  = (uint32_t)(krow << 4);
    const uint32_t kbase = sbase + KV_OFF + (uint32_t)((kg2 * 8 + krow) * 128);
    const uint32_t kcol0 = (uint32_t)(kg1 * 16);
    // ldmatrix addressing for PV B (V, trans, x2)
    const int i2 = lane & 15;
    const uint32_t vxor  = (uint32_t)((i2 & 7) << 4);
    const uint32_t vbase = sbase + KV_OFF + (uint32_t)(i2 * 128);

    // mask bitset: 64 words cover 2048 keys
    for (int j = wid; j < S_LEN / 32; j += 8) {
        int m = mask[b * S_LEN + j * 32 + lane];
        unsigned wv = __ballot_sync(0xFFFFFFFFu, m != 0);
        if (lane == 0) mask_words[j] = wv;
    }

    // ---- prologue: stage Q tile, build Q fp16 A-fragments in registers ----
    const float* Xbh = X + (size_t)b * S_LEN * DMODEL + (size_t)h * DPH;
    tile_load(sbase + STG_OFF, Xbh + (size_t)(qt * BM) * DMODEL, tid);
    CP_WAIT0();
    __syncthreads();

    uint32_t qa[4][4];                   // 4 k16-steps x 4 regs (m16n8k16 A)
#pragma unroll
    for (int ks = 0; ks < 4; ++ks) {
        int k0 = ks * 16 + 2 * qq;
        qa[ks][0] = pack_f16x2(stgf[lr * 64 + k0],           stgf[lr * 64 + k0 + 1]);
        qa[ks][1] = pack_f16x2(stgf[(lr + 8) * 64 + k0],     stgf[(lr + 8) * 64 + k0 + 1]);
        qa[ks][2] = pack_f16x2(stgf[lr * 64 + k0 + 8],       stgf[lr * 64 + k0 + 9]);
        qa[ks][3] = pack_f16x2(stgf[(lr + 8) * 64 + k0 + 8], stgf[(lr + 8) * 64 + k0 + 9]);
    }
    __syncthreads();

    // kick K/V tile 0
    tile_load(sbase + STG_OFF, Xbh, tid);

    // output accumulators + row sums
    float oa[8][4];
#pragma unroll
    for (int nb = 0; nb < 8; ++nb)
#pragma unroll
        for (int j = 0; j < 4; ++j) oa[nb][j] = 0.0f;
    float rs0 = 0.0f, rs1 = 0.0f;

    const int qrow0 = qt * BM + lr;
    float* dpr0 = dp ? dp + ((size_t)bh * S_LEN + qrow0) * S_LEN + 2 * qq : (float*)0;
    float* dpr1 = dpr0 ? dpr0 + 8 * (size_t)S_LEN : (float*)0;

#pragma unroll 1
    for (int kt = 0; kt < NKT; ++kt) {
        CP_WAIT0();
        __syncthreads();     // staging ready; prior compute done with KV

        // ---- convert staging fp32 -> fp16 KV tile (swizzled, 16KB) ----
#pragma unroll
        for (int i = 0; i < 8; ++i) {
            int idx = i * NTHREADS + tid;
            int key = idx >> 4, c4 = idx & 15;
            float4 v = *reinterpret_cast<const float4*>(stgf + idx * 4);
            uint32_t voff = (uint32_t)KV_OFF + (uint32_t)key * 128 +
                            (((uint32_t)(c4 * 8)) ^ ((uint32_t)(key & 7) << 4));
            *reinterpret_cast<uint2*>(smem + voff) =
                make_uint2(pack_f16x2(v.x, v.y), pack_f16x2(v.z, v.w));
        }
        __syncthreads();

        if (kt + 1 < NKT)
            tile_load(sbase + STG_OFF, Xbh + (size_t)((kt + 1) * BN) * DMODEL, tid);

        // ---- S = Q K^T (fp16 m16n8k16, fp32 accum) ----
        float sa[16][4];
#pragma unroll
        for (int nb = 0; nb < 16; ++nb)
#pragma unroll
            for (int j = 0; j < 4; ++j) sa[nb][j] = 0.0f;

#pragma unroll
        for (int ks = 0; ks < 4; ++ks) {
            uint32_t kss = (uint32_t)(ks * 32) + kcol0;      // k0*2 bytes + kg1 chunk
#pragma unroll
            for (int nb4 = 0; nb4 < 8; ++nb4) {              // 16 keys per iter
                uint32_t b0, b1, b2, b3;
                ldsm_x4(b0, b1, b2, b3, kbase + (uint32_t)(nb4 * 2048) + (kss ^ kxor));
                mma_f16(sa[2 * nb4],     qa[ks][0], qa[ks][1], qa[ks][2], qa[ks][3], b0, b1);
                mma_f16(sa[2 * nb4 + 1], qa[ks][0], qa[ks][1], qa[ks][2], qa[ks][3], b2, b3);
            }
        }

        // ---- scale, mask, write dot_prod, exp, pack P (fp16x2 = PV A-frags) ----
        uint32_t mwt0 = mask_words[kt * 4 + 0], mwt1 = mask_words[kt * 4 + 1];
        uint32_t mwt2 = mask_words[kt * 4 + 2], mwt3 = mask_words[kt * 4 + 3];
        bool tile_all = ((mwt0 & mwt1 & mwt2 & mwt3) == 0xFFFFFFFFu);

        uint32_t ph0[16], ph1[16];
#pragma unroll
        for (int nb = 0; nb < 16; ++nb) {
            float c0 = sa[nb][0] * 0.125f, c1 = sa[nb][1] * 0.125f;
            float c2 = sa[nb][2] * 0.125f, c3 = sa[nb][3] * 0.125f;
            if (!tile_all) {
                int col = nb * 8 + 2 * qq;
                uint32_t w = (nb < 4) ? mwt0 : (nb < 8) ? mwt1 : (nb < 12) ? mwt2 : mwt3;
                if (!((w >> (col & 31)) & 1u)) { c0 = -1e20f; c2 = -1e20f; }
                if (!((w >> ((col + 1) & 31)) & 1u)) { c1 = -1e20f; c3 = -1e20f; }
            }
            if (dpr0) {
                int coff = kt * BN + nb * 8;
                *reinterpret_cast<float2*>(dpr0 + coff) = make_float2(c0, c1);
                *reinterpret_cast<float2*>(dpr1 + coff) = make_float2(c2, c3);
            }
            // scaled p: keeps fp16 in range; scale cancels in O/rowsum ratio
            float p0 = __expf(c0) * P_SCALE, p1 = __expf(c1) * P_SCALE;
            float p2 = __expf(c2) * P_SCALE, p3 = __expf(c3) * P_SCALE;
            rs0 += p0 + p1;
            rs1 += p2 + p3;
            ph0[nb] = pack_f16x2(p0, p1);
            ph1[nb] = pack_f16x2(p2, p3);
        }

        // ---- O += P V (fp16), V from same KV tile via ldmatrix.trans ----
#pragma unroll
        for (int kg = 0; kg < 8; ++kg) {
            uint32_t a0 = ph0[2 * kg], a1 = ph1[2 * kg];
            uint32_t a2 = ph0[2 * kg + 1], a3 = ph1[2 * kg + 1];
#pragma unroll
            for (int nb = 0; nb < 8; ++nb) {
                uint32_t b0, b1;
                ldsm_x2t(b0, b1, vbase + (uint32_t)kg * 2048 + (((uint32_t)(nb * 16)) ^ vxor));
                mma_f16(oa[nb], a0, a1, a2, a3, b0, b1);
            }
        }
    }

    // ---- finalize: row sums (quad reduce), normalize, store out ----
    rs0 += __shfl_xor_sync(0xFFFFFFFFu, rs0, 1);
    rs0 += __shfl_xor_sync(0xFFFFFFFFu, rs0, 2);
    rs1 += __shfl_xor_sync(0xFFFFFFFFu, rs1, 1);
    rs1 += __shfl_xor_sync(0xFFFFFFFFu, rs1, 2);
    float inv0 = 1.0f / rs0, inv1 = 1.0f / rs1;

    if (out) {
        float* or0 = out + ((size_t)(b * S_LEN + qrow0)) * DMODEL + h * DPH + 2 * qq;
        float* or1 = or0 + 8 * (size_t)DMODEL;
#pragma unroll
        for (int nb = 0; nb < 8; ++nb) {
            *reinterpret_cast<float2*>(or0 + nb * 8) =
                make_float2(oa[nb][0] * inv0, oa[nb][1] * inv0);
            *reinterpret_cast<float2*>(or1 + nb * 8) =
                make_float2(oa[nb][2] * inv1, oa[nb][3] * inv1);
        }
    }
}

// ---------------- launch ----------------
extern "C" void kernel_launch(void* const* d_in, const int* in_sizes, int n_in,
                              void* d_out, int out_size) {
    const float* X  = (const float*)d_in[0];
    const int* mask = (const int*)d_in[1];

    float* out = (float*)0;
    float* dp  = (float*)0;
    size_t os = (size_t)out_size;
    if (os >= OUT_ELEMS + DOT_ELEMS) {
        out = (float*)d_out;
        dp  = (float*)d_out + OUT_ELEMS;
    } else if (os == DOT_ELEMS) {
        dp = (float*)d_out;
    } else {
        out = (float*)d_out;
    }

    cudaFuncSetAttribute(mha_kernel, cudaFuncAttributeMaxDynamicSharedMemorySize, SMEM_BYTES);
    dim3 grid(S_LEN / BM, 32);
    mha_kernel<<<grid, NTHREADS, SMEM_BYTES>>>(X, mask, out, dp);
}